// round 13
// baseline (speedup 1.0000x reference)
#include <cuda_runtime.h>
#include <cuda_fp16.h>
#include <cstdint>

// ---------------- scratch (__device__ globals; no allocation allowed) -------
__device__ __half g_xs[4096 * 1024];            // x as fp16
__device__ __half g_ks[4096 * 1024];            // K projection fp16
__device__ __half g_att[4096 * 1024];           // attention out fp16
__device__ __half g_wk[1024 * 1024];            // W_attn K-slice, [n][k] fp16
__device__ __half g_wp[1024 * 1024];            // W_proj, [n][k] fp16

// ---------------- PTX helpers (all compute_103-safe) ------------------------
__device__ __forceinline__ float fast_exp2(float x) {
    float y; asm("ex2.approx.ftz.f32 %0, %1;" : "=f"(y) : "f"(x)); return y;
}
__device__ __forceinline__ uint32_t smem_u32(const void* p) {
    uint32_t a;
    asm("{ .reg .u64 t; cvta.to.shared.u64 t, %1; cvt.u32.u64 %0, t; }" : "=r"(a) : "l"(p));
    return a;
}
__device__ __forceinline__ void cp_async16(uint32_t dst, const void* src) {
    asm volatile("cp.async.cg.shared.global [%0], [%1], 16;" :: "r"(dst), "l"(src));
}
__device__ __forceinline__ void cp_commit() {
    asm volatile("cp.async.commit_group;" ::: "memory");
}
__device__ __forceinline__ void cp_wait1() {
    asm volatile("cp.async.wait_group 1;" ::: "memory");
}
__device__ __forceinline__ void cp_wait0() {
    asm volatile("cp.async.wait_group 0;" ::: "memory");
}
__device__ __forceinline__ void ldsm4(uint32_t& r0, uint32_t& r1, uint32_t& r2,
                                      uint32_t& r3, uint32_t addr) {
    asm volatile("ldmatrix.sync.aligned.m8n8.x4.shared.b16 {%0,%1,%2,%3}, [%4];"
                 : "=r"(r0), "=r"(r1), "=r"(r2), "=r"(r3) : "r"(addr));
}
__device__ __forceinline__ void ldsm4t(uint32_t& r0, uint32_t& r1, uint32_t& r2,
                                       uint32_t& r3, uint32_t addr) {
    asm volatile("ldmatrix.sync.aligned.m8n8.x4.trans.shared.b16 {%0,%1,%2,%3}, [%4];"
                 : "=r"(r0), "=r"(r1), "=r"(r2), "=r"(r3) : "r"(addr));
}
__device__ __forceinline__ void mma_f16(float* c, const uint32_t* a,
                                        uint32_t b0, uint32_t b1) {
    asm volatile(
        "mma.sync.aligned.m16n8k16.row.col.f32.f16.f16.f32 "
        "{%0,%1,%2,%3}, {%4,%5,%6,%7}, {%8,%9}, {%0,%1,%2,%3};"
        : "+f"(c[0]), "+f"(c[1]), "+f"(c[2]), "+f"(c[3])
        : "r"(a[0]), "r"(a[1]), "r"(a[2]), "r"(a[3]), "r"(b0), "r"(b1));
}
__device__ __forceinline__ uint32_t pack_h2(float a, float b) {
    __half2 h = __float22half2_rn(make_float2(a, b));
    return *(uint32_t*)&h;
}

// ---------------- merged prep: x->fp16; W transposes (single fp16) ----------
__global__ __launch_bounds__(256) void prep_kernel(
    const float* __restrict__ X, __half* __restrict__ XO,
    const float* __restrict__ Wk, const float* __restrict__ Wp,
    __half* __restrict__ WkO, __half* __restrict__ WpO)
{
    __shared__ float t[32][33];
    int bid = blockIdx.x;
    if (bid < 4096) {
        int i = bid * 256 + threadIdx.x;
        float4 v = ((const float4*)X)[i];
        ((__half2*)XO)[i * 2]     = __float22half2_rn(make_float2(v.x, v.y));
        ((__half2*)XO)[i * 2 + 1] = __float22half2_rn(make_float2(v.z, v.w));
        return;
    }
    bid -= 4096;
    const float* W; __half* O; int ldw;
    if (bid < 1024) { W = Wk; ldw = 3072; O = WkO; }
    else { bid -= 1024; W = Wp; ldw = 1024; O = WpO; }
    int n0 = (bid & 31) * 32, k0 = (bid >> 5) * 32;
    int tx = threadIdx.x & 31, ty = threadIdx.x >> 5;
#pragma unroll
    for (int p = 0; p < 4; p++)
        t[ty + 8 * p][tx] = W[(size_t)(k0 + ty + 8 * p) * ldw + n0 + tx];
    __syncthreads();
#pragma unroll
    for (int p = 0; p < 4; p++)
        O[(size_t)(n0 + ty + 8 * p) * 1024 + k0 + tx] =
            __float2half_rn(t[tx][ty + 8 * p]);
}

// ---------------- tensor-core GEMM: C = A @ B^T + bias (single fp16) --------
// Tile M=128, N=64, BK=64, 8 warps (4m x 2n, warp 32x32), double-buffered.
// occ 4: 512 CTAs fit in ONE wave (148*4=592 slots).
#define ROWB 144
#define GB_OFF 18432
#define GSTAGE 27648

__global__ __launch_bounds__(256, 4) void gemm_mma(
    const __half* __restrict__ A, const __half* __restrict__ B,
    const float* __restrict__ bias, float* __restrict__ C,
    __half* __restrict__ Ch)
{
    extern __shared__ char smem[];
    const uint32_t sb = smem_u32(smem);
    const int tid = threadIdx.x;
    const int wid = tid >> 5;
    const int lane = tid & 31;
    const int wm = wid >> 1;
    const int wn = wid & 1;
    const int m0 = blockIdx.y * 128, n0 = blockIdx.x * 64;

    const int lrow = tid >> 3;
    const int lkc = tid & 7;

    const uint32_t a_off = (uint32_t)((wm * 32 + (lane & 15)) * ROWB + (lane >> 4) * 16);
    const uint32_t b_off = (uint32_t)((wn * 32 + (lane & 15)) * ROWB + (lane >> 4) * 16);

    float acc[2][4][4];
#pragma unroll
    for (int i = 0; i < 2; i++)
#pragma unroll
        for (int j = 0; j < 4; j++)
#pragma unroll
            for (int r = 0; r < 4; r++) acc[i][j][r] = 0.0f;

#pragma unroll
    for (int q = 0; q < 4; q++) {
        int row = lrow + q * 32;
        cp_async16(sb + row * ROWB + lkc * 16,
                   (const char*)A + (size_t)(m0 + row) * 2048 + lkc * 16);
    }
#pragma unroll
    for (int q = 0; q < 2; q++) {
        int row = lrow + q * 32;
        cp_async16(sb + GB_OFF + row * ROWB + lkc * 16,
                   (const char*)B + (size_t)(n0 + row) * 2048 + lkc * 16);
    }
    cp_commit();

    for (int c = 0; c < 16; c++) {
        const uint32_t st = (uint32_t)(c & 1) * GSTAGE;
        if (c + 1 < 16) {
            const uint32_t st2 = (uint32_t)((c + 1) & 1) * GSTAGE;
            const size_t ko = (size_t)(c + 1) * 128;
#pragma unroll
            for (int q = 0; q < 4; q++) {
                int row = lrow + q * 32;
                cp_async16(st2 + sb + row * ROWB + lkc * 16,
                           (const char*)A + (size_t)(m0 + row) * 2048 + ko + lkc * 16);
            }
#pragma unroll
            for (int q = 0; q < 2; q++) {
                int row = lrow + q * 32;
                cp_async16(st2 + sb + GB_OFF + row * ROWB + lkc * 16,
                           (const char*)B + (size_t)(n0 + row) * 2048 + ko + lkc * 16);
            }
            cp_commit();
            cp_wait1();
        } else {
            cp_wait0();
        }
        __syncthreads();

#pragma unroll
        for (int kk = 0; kk < 4; kk++) {
            uint32_t bh[2][4];
#pragma unroll
            for (int p = 0; p < 2; p++) {
                uint32_t addr = st + sb + GB_OFF + b_off + (uint32_t)(p * 16 * ROWB) + kk * 32;
                ldsm4(bh[p][0], bh[p][1], bh[p][2], bh[p][3], addr);
            }
            uint32_t ah[2][4];
#pragma unroll
            for (int mf = 0; mf < 2; mf++) {
                uint32_t addr = st + sb + a_off + (uint32_t)(mf * 16 * ROWB) + kk * 32;
                ldsm4(ah[mf][0], ah[mf][1], ah[mf][2], ah[mf][3], addr);
            }
#pragma unroll
            for (int mf = 0; mf < 2; mf++)
#pragma unroll
                for (int nf = 0; nf < 4; nf++) {
                    const int p = nf >> 1, hh = nf & 1;
                    mma_f16(acc[mf][nf], ah[mf], bh[p][hh], bh[p][2 + hh]);
                }
        }
        __syncthreads();
    }

    // epilogue
#pragma unroll
    for (int nf = 0; nf < 4; nf++) {
        int n = n0 + wn * 32 + nf * 8 + (lane & 3) * 2;
        float2 bv = *(const float2*)(bias + n);
#pragma unroll
        for (int mf = 0; mf < 2; mf++) {
            int m = m0 + wm * 32 + mf * 16 + (lane >> 2);
            float2 o0 = {acc[mf][nf][0] + bv.x, acc[mf][nf][1] + bv.y};
            float2 o1 = {acc[mf][nf][2] + bv.x, acc[mf][nf][3] + bv.y};
            if (Ch) {
                *(__half2*)(Ch + (size_t)m * 1024 + n) =
                    __float22half2_rn(make_float2(o0.x, o0.y));
                *(__half2*)(Ch + (size_t)(m + 8) * 1024 + n) =
                    __float22half2_rn(make_float2(o1.x, o1.y));
            } else {
                *(float2*)(C + (size_t)m * 1024 + n) = o0;
                *(float2*)(C + (size_t)(m + 8) * 1024 + n) = o1;
            }
        }
    }
}

// ---------------- FA2-style attention (single-fp16 K throughout) ------------
#define AK0 18432
#define AKST 18432
#define ATTN_SMEM_B (18432 + 2 * 18432)

__global__ __launch_bounds__(256, 2) void attn_mma(
    const __half* __restrict__ K, __half* __restrict__ Out)
{
    extern __shared__ char smem[];
    const uint32_t sb = smem_u32(smem);
    const int tid = threadIdx.x;
    const int wid = tid >> 5;
    const int lane = tid & 31;
    const int g = lane >> 2;
    const int tq = lane & 3;
    const int b = blockIdx.y >> 4;
    const int h = blockIdx.y & 15;
    const int q0 = blockIdx.x * 128;

    const char* Kb = (const char*)K + (size_t)b * 2048 * 2048 + h * 128;
    const float SC = 0.125f * 1.4426950408889634f;

#pragma unroll
    for (int q = 0; q < 4; q++) {
        int u = tid + q * 256;
        int row = u >> 3, c = u & 7;
        cp_async16(sb + row * ROWB + c * 16,
                   Kb + (size_t)(q0 + row) * 2048 + c * 16);
    }
#pragma unroll
    for (int q = 0; q < 4; q++) {
        int u = tid + q * 256;
        int row = u >> 3, c = u & 7;
        cp_async16(sb + AK0 + row * ROWB + c * 16, Kb + (size_t)row * 2048 + c * 16);
    }
    cp_commit();

    float m0 = -1e30f, m1 = -1e30f, l0 = 0.0f, l1 = 0.0f;
    float o[8][4];
#pragma unroll
    for (int nf = 0; nf < 8; nf++)
#pragma unroll
        for (int r = 0; r < 4; r++) o[nf][r] = 0.0f;

    const uint32_t qa_off = (uint32_t)((wid * 16 + (lane & 15)) * ROWB + (lane >> 4) * 16);
    const uint32_t kb_row = (uint32_t)((lane & 15) * ROWB + (lane >> 4) * 16);

    for (int kt = 0; kt < 16; kt++) {
        const uint32_t st = sb + AK0 + (uint32_t)(kt & 1) * AKST;
        if (kt + 1 < 16) {
            const uint32_t st2 = sb + AK0 + (uint32_t)((kt + 1) & 1) * AKST;
            const size_t j0 = (size_t)(kt + 1) * 128;
#pragma unroll
            for (int q = 0; q < 4; q++) {
                int u = tid + q * 256;
                int row = u >> 3, c = u & 7;
                cp_async16(st2 + row * ROWB + c * 16, Kb + (j0 + row) * 2048 + c * 16);
            }
            cp_commit();
            cp_wait1();
        } else {
            cp_wait0();
        }
        __syncthreads();

        // ---- S = Q K^T ----
        float s[16][4];
#pragma unroll
        for (int nf = 0; nf < 16; nf++)
#pragma unroll
            for (int r = 0; r < 4; r++) s[nf][r] = 0.0f;

#pragma unroll
        for (int kk = 0; kk < 4; kk++) {
            uint32_t qh[4];
            ldsm4(qh[0], qh[1], qh[2], qh[3], sb + qa_off + kk * 32);
#pragma unroll
            for (int nb = 0; nb < 8; nb++) {
                uint32_t kh[4];
                uint32_t addr = st + kb_row + (uint32_t)(nb * 16 * ROWB) + kk * 32;
                ldsm4(kh[0], kh[1], kh[2], kh[3], addr);
#pragma unroll
                for (int hh = 0; hh < 2; hh++)
                    mma_f16(s[2 * nb + hh], qh, kh[hh], kh[2 + hh]);
            }
        }

        // ---- online softmax (scale folded) ----
        float mx0 = -1e30f, mx1 = -1e30f;
#pragma unroll
        for (int nf = 0; nf < 16; nf++) {
            mx0 = fmaxf(mx0, fmaxf(s[nf][0], s[nf][1]));
            mx1 = fmaxf(mx1, fmaxf(s[nf][2], s[nf][3]));
        }
        mx0 = fmaxf(mx0, __shfl_xor_sync(0xffffffffu, mx0, 1));
        mx0 = fmaxf(mx0, __shfl_xor_sync(0xffffffffu, mx0, 2));
        mx1 = fmaxf(mx1, __shfl_xor_sync(0xffffffffu, mx1, 1));
        mx1 = fmaxf(mx1, __shfl_xor_sync(0xffffffffu, mx1, 2));
        float mn0 = fmaxf(m0, mx0), mn1 = fmaxf(m1, mx1);
        float c0 = fast_exp2((m0 - mn0) * SC), c1 = fast_exp2((m1 - mn1) * SC);
        m0 = mn0; m1 = mn1;
        l0 *= c0; l1 *= c1;
#pragma unroll
        for (int nf = 0; nf < 8; nf++) {
            o[nf][0] *= c0; o[nf][1] *= c0;
            o[nf][2] *= c1; o[nf][3] *= c1;
        }
        const float b0s = -mn0 * SC, b1s = -mn1 * SC;
        float rs0 = 0.0f, rs1 = 0.0f;
#pragma unroll
        for (int nf = 0; nf < 16; nf++) {
            s[nf][0] = fast_exp2(fmaf(s[nf][0], SC, b0s));
            s[nf][1] = fast_exp2(fmaf(s[nf][1], SC, b0s));
            s[nf][2] = fast_exp2(fmaf(s[nf][2], SC, b1s));
            s[nf][3] = fast_exp2(fmaf(s[nf][3], SC, b1s));
            rs0 += s[nf][0] + s[nf][1];
            rs1 += s[nf][2] + s[nf][3];
        }
        rs0 += __shfl_xor_sync(0xffffffffu, rs0, 1);
        rs0 += __shfl_xor_sync(0xffffffffu, rs0, 2);
        rs1 += __shfl_xor_sync(0xffffffffu, rs1, 1);
        rs1 += __shfl_xor_sync(0xffffffffu, rs1, 2);
        l0 += rs0; l1 += rs1;

        // ---- O += P V (single term; V via ldsm.trans) ----
#pragma unroll
        for (int t = 0; t < 8; t++) {
            uint32_t ph[4];
            ph[0] = pack_h2(s[2 * t][0], s[2 * t][1]);
            ph[1] = pack_h2(s[2 * t][2], s[2 * t][3]);
            ph[2] = pack_h2(s[2 * t + 1][0], s[2 * t + 1][1]);
            ph[3] = pack_h2(s[2 * t + 1][2], s[2 * t + 1][3]);
#pragma unroll
            for (int nb = 0; nb < 4; nb++) {
                uint32_t vh[4];
                uint32_t addr = st + kb_row + (uint32_t)(t * 16 * ROWB) + nb * 32;
                ldsm4t(vh[0], vh[1], vh[2], vh[3], addr);
#pragma unroll
                for (int hh = 0; hh < 2; hh++)
                    mma_f16(o[2 * nb + hh], ph, vh[2 * hh], vh[2 * hh + 1]);
            }
        }
        __syncthreads();
    }

    // ---- epilogue ----
    float inv0 = 1.0f / l0, inv1 = 1.0f / l1;
    int mr0 = q0 + wid * 16 + g;
#pragma unroll
    for (int nf = 0; nf < 8; nf++) {
        int d = h * 64 + nf * 8 + tq * 2;
        size_t i0 = ((size_t)b * 2048 + mr0) * 1024 + d;
        size_t i1 = i0 + 8 * 1024;
        *(__half2*)(Out + i0) = __float22half2_rn(
            make_float2(o[nf][0] * inv0, o[nf][1] * inv0));
        *(__half2*)(Out + i1) = __float22half2_rn(
            make_float2(o[nf][2] * inv1, o[nf][3] * inv1));
    }
}

// ---------------------------------------------------------------------------
extern "C" void kernel_launch(void* const* d_in, const int* in_sizes, int n_in,
                              void* d_out, int out_size) {
    const float* x      = (const float*)d_in[0];  // (2, 2048, 1024)
    const float* W_attn = (const float*)d_in[1];  // (1024, 3072)
    const float* b_attn = (const float*)d_in[2];  // (3072,)
    const float* W_proj = (const float*)d_in[3];  // (1024, 1024)
    const float* b_proj = (const float*)d_in[4];  // (1024,)
    float* out = (float*)d_out;                   // (2, 2048, 1024)

    __half *xs, *ks, *att, *wk, *wp;
    cudaGetSymbolAddress((void**)&xs, g_xs);
    cudaGetSymbolAddress((void**)&ks, g_ks);
    cudaGetSymbolAddress((void**)&att, g_att);
    cudaGetSymbolAddress((void**)&wk, g_wk);
    cudaGetSymbolAddress((void**)&wp, g_wp);

    const int GEMM_SMEM = 2 * GSTAGE;  // 55296
    cudaFuncSetAttribute(gemm_mma,
                         cudaFuncAttributeMaxDynamicSharedMemorySize, GEMM_SMEM);
    cudaFuncSetAttribute(attn_mma,
                         cudaFuncAttributeMaxDynamicSharedMemorySize, ATTN_SMEM_B);

    // Prep (one launch)
    prep_kernel<<<6144, 256>>>(x, xs, W_attn + 1024, W_proj, wk, wp);

    // Stage 1: K = x @ W_attn[:, D:2D] + b  -> single fp16
    gemm_mma<<<dim3(16, 32), 256, GEMM_SMEM>>>(xs, wk, b_attn + 1024, nullptr, ks);

    // Stage 2: FA2 attention -> att fp16
    attn_mma<<<dim3(16, 32), 256, ATTN_SMEM_B>>>(ks, att);

    // Stage 3: out = att @ W_proj + b_proj (fp32 out)
    gemm_mma<<<dim3(16, 32), 256, GEMM_SMEM>>>(att, wp, b_proj, out, nullptr);
}

// round 14
// speedup vs baseline: 1.0294x; 1.0294x over previous
#include <cuda_runtime.h>
#include <cuda_fp16.h>
#include <cstdint>

// ---------------- scratch (__device__ globals; no allocation allowed) -------
__device__ __half g_xs[4096 * 1024];            // x as fp16
__device__ __half g_ks[4096 * 1024];            // K projection fp16
__device__ __half g_att[4096 * 1024];           // attention out fp16
__device__ __half g_wk[1024 * 1024];            // W_attn K-slice, [n][k] fp16
__device__ __half g_wp[1024 * 1024];            // W_proj, [n][k] fp16

// ---------------- PTX helpers (all compute_103-safe) ------------------------
__device__ __forceinline__ float fast_exp2(float x) {
    float y; asm("ex2.approx.ftz.f32 %0, %1;" : "=f"(y) : "f"(x)); return y;
}
__device__ __forceinline__ uint32_t smem_u32(const void* p) {
    uint32_t a;
    asm("{ .reg .u64 t; cvta.to.shared.u64 t, %1; cvt.u32.u64 %0, t; }" : "=r"(a) : "l"(p));
    return a;
}
__device__ __forceinline__ void cp_async16(uint32_t dst, const void* src) {
    asm volatile("cp.async.cg.shared.global [%0], [%1], 16;" :: "r"(dst), "l"(src));
}
__device__ __forceinline__ void cp_commit() {
    asm volatile("cp.async.commit_group;" ::: "memory");
}
__device__ __forceinline__ void cp_wait1() {
    asm volatile("cp.async.wait_group 1;" ::: "memory");
}
__device__ __forceinline__ void cp_wait2() {
    asm volatile("cp.async.wait_group 2;" ::: "memory");
}
__device__ __forceinline__ void cp_wait0() {
    asm volatile("cp.async.wait_group 0;" ::: "memory");
}
__device__ __forceinline__ void ldsm4(uint32_t& r0, uint32_t& r1, uint32_t& r2,
                                      uint32_t& r3, uint32_t addr) {
    asm volatile("ldmatrix.sync.aligned.m8n8.x4.shared.b16 {%0,%1,%2,%3}, [%4];"
                 : "=r"(r0), "=r"(r1), "=r"(r2), "=r"(r3) : "r"(addr));
}
__device__ __forceinline__ void ldsm4t(uint32_t& r0, uint32_t& r1, uint32_t& r2,
                                       uint32_t& r3, uint32_t addr) {
    asm volatile("ldmatrix.sync.aligned.m8n8.x4.trans.shared.b16 {%0,%1,%2,%3}, [%4];"
                 : "=r"(r0), "=r"(r1), "=r"(r2), "=r"(r3) : "r"(addr));
}
__device__ __forceinline__ void mma_f16(float* c, const uint32_t* a,
                                        uint32_t b0, uint32_t b1) {
    asm volatile(
        "mma.sync.aligned.m16n8k16.row.col.f32.f16.f16.f32 "
        "{%0,%1,%2,%3}, {%4,%5,%6,%7}, {%8,%9}, {%0,%1,%2,%3};"
        : "+f"(c[0]), "+f"(c[1]), "+f"(c[2]), "+f"(c[3])
        : "r"(a[0]), "r"(a[1]), "r"(a[2]), "r"(a[3]), "r"(b0), "r"(b1));
}
__device__ __forceinline__ uint32_t pack_h2(float a, float b) {
    __half2 h = __float22half2_rn(make_float2(a, b));
    return *(uint32_t*)&h;
}

// ---------------- merged prep: x->fp16; W transposes (single fp16) ----------
__global__ __launch_bounds__(256) void prep_kernel(
    const float* __restrict__ X, __half* __restrict__ XO,
    const float* __restrict__ Wk, const float* __restrict__ Wp,
    __half* __restrict__ WkO, __half* __restrict__ WpO)
{
    __shared__ float t[32][33];
    int bid = blockIdx.x;
    if (bid < 4096) {
        int i = bid * 256 + threadIdx.x;
        float4 v = ((const float4*)X)[i];
        ((__half2*)XO)[i * 2]     = __float22half2_rn(make_float2(v.x, v.y));
        ((__half2*)XO)[i * 2 + 1] = __float22half2_rn(make_float2(v.z, v.w));
        return;
    }
    bid -= 4096;
    const float* W; __half* O; int ldw;
    if (bid < 1024) { W = Wk; ldw = 3072; O = WkO; }
    else { bid -= 1024; W = Wp; ldw = 1024; O = WpO; }
    int n0 = (bid & 31) * 32, k0 = (bid >> 5) * 32;
    int tx = threadIdx.x & 31, ty = threadIdx.x >> 5;
#pragma unroll
    for (int p = 0; p < 4; p++)
        t[ty + 8 * p][tx] = W[(size_t)(k0 + ty + 8 * p) * ldw + n0 + tx];
    __syncthreads();
#pragma unroll
    for (int p = 0; p < 4; p++)
        O[(size_t)(n0 + ty + 8 * p) * 1024 + k0 + tx] =
            __float2half_rn(t[tx][ty + 8 * p]);
}

// ---------------- tensor-core GEMM: C = A @ B^T + bias (single fp16) --------
// Tile M=256, N=128, BK=32, 512 threads (16 warps, warp 64x32), 4-stage
// cp.async pipeline, ONE CTA per SM (128 CTAs, single balanced wave).
// Stage layout: rows 0..255 = A (80B rows), rows 256..383 = B. 30720 B/stage.
#define G2_ROWB 80
#define G2_STAGE 30720
#define G2_SMEM (4 * G2_STAGE)   // 122880

__global__ __launch_bounds__(512, 1) void gemm_mma(
    const __half* __restrict__ A, const __half* __restrict__ B,
    const float* __restrict__ bias, float* __restrict__ C,
    __half* __restrict__ Ch)
{
    extern __shared__ char smem[];
    const uint32_t sb = smem_u32(smem);
    const int tid = threadIdx.x;
    const int wid = tid >> 5;       // 0..15
    const int lane = tid & 31;
    const int wm = wid >> 2;        // 0..3, 64 rows each
    const int wn = wid & 3;         // 0..3, 32 cols each
    const int m0 = blockIdx.y * 256, n0 = blockIdx.x * 128;

    // loader: 1536 16B-units per chunk, 3 per thread; rows<256 = A, else B.
    const uint32_t a_off = (uint32_t)((wm * 64 + (lane & 15)) * G2_ROWB + (lane >> 4) * 16);
    const uint32_t b_off = (uint32_t)(256 * G2_ROWB
                                      + (wn * 32 + (lane & 15)) * G2_ROWB + (lane >> 4) * 16);

    float acc[4][4][4];
#pragma unroll
    for (int i = 0; i < 4; i++)
#pragma unroll
        for (int j = 0; j < 4; j++)
#pragma unroll
            for (int r = 0; r < 4; r++) acc[i][j][r] = 0.0f;

    // chunk issuer: chunk c covers k bytes [c*64, c*64+64)
#define G2_ISSUE(c, stg)                                                        \
    do {                                                                        \
        _Pragma("unroll")                                                       \
        for (int p = 0; p < 3; p++) {                                           \
            int u = tid + p * 512;                                              \
            int row = u >> 2, c16 = u & 3;                                      \
            const char* src = (row < 256)                                       \
                ? (const char*)A + (size_t)(m0 + row) * 2048 + (c) * 64 + c16 * 16 \
                : (const char*)B + (size_t)(n0 + row - 256) * 2048 + (c) * 64 + c16 * 16; \
            cp_async16(sb + (stg) + row * G2_ROWB + c16 * 16, src);             \
        }                                                                       \
    } while (0)

    // prologue: chunks 0,1,2
#pragma unroll
    for (int c = 0; c < 3; c++) {
        G2_ISSUE(c, (uint32_t)c * G2_STAGE);
        cp_commit();
    }

    for (int c = 0; c < 32; c++) {
        cp_wait2();           // chunk c's group complete (3 pending -> <=2)
        __syncthreads();      // all warps done with chunk c-1 compute + data visible
        if (c + 3 < 32) {
            G2_ISSUE(c + 3, (uint32_t)((c + 3) & 3) * G2_STAGE);
        }
        cp_commit();          // empty group in tail keeps accounting uniform

        const uint32_t st = (uint32_t)(c & 3) * G2_STAGE;
#pragma unroll
        for (int kk = 0; kk < 2; kk++) {
            uint32_t bh[2][4];
#pragma unroll
            for (int p = 0; p < 2; p++) {
                uint32_t addr = sb + st + b_off + (uint32_t)(p * 16 * G2_ROWB) + kk * 32;
                ldsm4(bh[p][0], bh[p][1], bh[p][2], bh[p][3], addr);
            }
            uint32_t ah[4][4];
#pragma unroll
            for (int mf = 0; mf < 4; mf++) {
                uint32_t addr = sb + st + a_off + (uint32_t)(mf * 16 * G2_ROWB) + kk * 32;
                ldsm4(ah[mf][0], ah[mf][1], ah[mf][2], ah[mf][3], addr);
            }
#pragma unroll
            for (int mf = 0; mf < 4; mf++)
#pragma unroll
                for (int nf = 0; nf < 4; nf++) {
                    const int p = nf >> 1, hh = nf & 1;
                    mma_f16(acc[mf][nf], ah[mf], bh[p][hh], bh[p][2 + hh]);
                }
        }
    }

    // epilogue
#pragma unroll
    for (int nf = 0; nf < 4; nf++) {
        int n = n0 + wn * 32 + nf * 8 + (lane & 3) * 2;
        float2 bv = *(const float2*)(bias + n);
#pragma unroll
        for (int mf = 0; mf < 4; mf++) {
            int m = m0 + wm * 64 + mf * 16 + (lane >> 2);
            float2 o0 = {acc[mf][nf][0] + bv.x, acc[mf][nf][1] + bv.y};
            float2 o1 = {acc[mf][nf][2] + bv.x, acc[mf][nf][3] + bv.y};
            if (Ch) {
                *(__half2*)(Ch + (size_t)m * 1024 + n) =
                    __float22half2_rn(make_float2(o0.x, o0.y));
                *(__half2*)(Ch + (size_t)(m + 8) * 1024 + n) =
                    __float22half2_rn(make_float2(o1.x, o1.y));
            } else {
                *(float2*)(C + (size_t)m * 1024 + n) = o0;
                *(float2*)(C + (size_t)(m + 8) * 1024 + n) = o1;
            }
        }
    }
}

// ---------------- FA2-style attention (single-fp16 K throughout) ------------
#define ROWB 144
#define AK0 18432
#define AKST 18432
#define ATTN_SMEM_B (18432 + 2 * 18432)

__global__ __launch_bounds__(256, 2) void attn_mma(
    const __half* __restrict__ K, __half* __restrict__ Out)
{
    extern __shared__ char smem[];
    const uint32_t sb = smem_u32(smem);
    const int tid = threadIdx.x;
    const int wid = tid >> 5;
    const int lane = tid & 31;
    const int g = lane >> 2;
    const int tq = lane & 3;
    const int b = blockIdx.y >> 4;
    const int h = blockIdx.y & 15;
    const int q0 = blockIdx.x * 128;

    const char* Kb = (const char*)K + (size_t)b * 2048 * 2048 + h * 128;
    const float SC = 0.125f * 1.4426950408889634f;

#pragma unroll
    for (int q = 0; q < 4; q++) {
        int u = tid + q * 256;
        int row = u >> 3, c = u & 7;
        cp_async16(sb + row * ROWB + c * 16,
                   Kb + (size_t)(q0 + row) * 2048 + c * 16);
    }
#pragma unroll
    for (int q = 0; q < 4; q++) {
        int u = tid + q * 256;
        int row = u >> 3, c = u & 7;
        cp_async16(sb + AK0 + row * ROWB + c * 16, Kb + (size_t)row * 2048 + c * 16);
    }
    cp_commit();

    float m0 = -1e30f, m1 = -1e30f, l0 = 0.0f, l1 = 0.0f;
    float o[8][4];
#pragma unroll
    for (int nf = 0; nf < 8; nf++)
#pragma unroll
        for (int r = 0; r < 4; r++) o[nf][r] = 0.0f;

    const uint32_t qa_off = (uint32_t)((wid * 16 + (lane & 15)) * ROWB + (lane >> 4) * 16);
    const uint32_t kb_row = (uint32_t)((lane & 15) * ROWB + (lane >> 4) * 16);

    for (int kt = 0; kt < 16; kt++) {
        const uint32_t st = sb + AK0 + (uint32_t)(kt & 1) * AKST;
        if (kt + 1 < 16) {
            const uint32_t st2 = sb + AK0 + (uint32_t)((kt + 1) & 1) * AKST;
            const size_t j0 = (size_t)(kt + 1) * 128;
#pragma unroll
            for (int q = 0; q < 4; q++) {
                int u = tid + q * 256;
                int row = u >> 3, c = u & 7;
                cp_async16(st2 + row * ROWB + c * 16, Kb + (j0 + row) * 2048 + c * 16);
            }
            cp_commit();
            cp_wait1();
        } else {
            cp_wait0();
        }
        __syncthreads();

        // ---- S = Q K^T ----
        float s[16][4];
#pragma unroll
        for (int nf = 0; nf < 16; nf++)
#pragma unroll
            for (int r = 0; r < 4; r++) s[nf][r] = 0.0f;

#pragma unroll
        for (int kk = 0; kk < 4; kk++) {
            uint32_t qh[4];
            ldsm4(qh[0], qh[1], qh[2], qh[3], sb + qa_off + kk * 32);
#pragma unroll
            for (int nb = 0; nb < 8; nb++) {
                uint32_t kh[4];
                uint32_t addr = st + kb_row + (uint32_t)(nb * 16 * ROWB) + kk * 32;
                ldsm4(kh[0], kh[1], kh[2], kh[3], addr);
#pragma unroll
                for (int hh = 0; hh < 2; hh++)
                    mma_f16(s[2 * nb + hh], qh, kh[hh], kh[2 + hh]);
            }
        }

        // ---- online softmax (scale folded) ----
        float mx0 = -1e30f, mx1 = -1e30f;
#pragma unroll
        for (int nf = 0; nf < 16; nf++) {
            mx0 = fmaxf(mx0, fmaxf(s[nf][0], s[nf][1]));
            mx1 = fmaxf(mx1, fmaxf(s[nf][2], s[nf][3]));
        }
        mx0 = fmaxf(mx0, __shfl_xor_sync(0xffffffffu, mx0, 1));
        mx0 = fmaxf(mx0, __shfl_xor_sync(0xffffffffu, mx0, 2));
        mx1 = fmaxf(mx1, __shfl_xor_sync(0xffffffffu, mx1, 1));
        mx1 = fmaxf(mx1, __shfl_xor_sync(0xffffffffu, mx1, 2));
        float mn0 = fmaxf(m0, mx0), mn1 = fmaxf(m1, mx1);
        float c0 = fast_exp2((m0 - mn0) * SC), c1 = fast_exp2((m1 - mn1) * SC);
        m0 = mn0; m1 = mn1;
        l0 *= c0; l1 *= c1;
#pragma unroll
        for (int nf = 0; nf < 8; nf++) {
            o[nf][0] *= c0; o[nf][1] *= c0;
            o[nf][2] *= c1; o[nf][3] *= c1;
        }
        const float b0s = -mn0 * SC, b1s = -mn1 * SC;
        float rs0 = 0.0f, rs1 = 0.0f;
#pragma unroll
        for (int nf = 0; nf < 16; nf++) {
            s[nf][0] = fast_exp2(fmaf(s[nf][0], SC, b0s));
            s[nf][1] = fast_exp2(fmaf(s[nf][1], SC, b0s));
            s[nf][2] = fast_exp2(fmaf(s[nf][2], SC, b1s));
            s[nf][3] = fast_exp2(fmaf(s[nf][3], SC, b1s));
            rs0 += s[nf][0] + s[nf][1];
            rs1 += s[nf][2] + s[nf][3];
        }
        rs0 += __shfl_xor_sync(0xffffffffu, rs0, 1);
        rs0 += __shfl_xor_sync(0xffffffffu, rs0, 2);
        rs1 += __shfl_xor_sync(0xffffffffu, rs1, 1);
        rs1 += __shfl_xor_sync(0xffffffffu, rs1, 2);
        l0 += rs0; l1 += rs1;

        // ---- O += P V (single term; V via ldsm.trans) ----
#pragma unroll
        for (int t = 0; t < 8; t++) {
            uint32_t ph[4];
            ph[0] = pack_h2(s[2 * t][0], s[2 * t][1]);
            ph[1] = pack_h2(s[2 * t][2], s[2 * t][3]);
            ph[2] = pack_h2(s[2 * t + 1][0], s[2 * t + 1][1]);
            ph[3] = pack_h2(s[2 * t + 1][2], s[2 * t + 1][3]);
#pragma unroll
            for (int nb = 0; nb < 4; nb++) {
                uint32_t vh[4];
                uint32_t addr = st + kb_row + (uint32_t)(t * 16 * ROWB) + nb * 32;
                ldsm4t(vh[0], vh[1], vh[2], vh[3], addr);
#pragma unroll
                for (int hh = 0; hh < 2; hh++)
                    mma_f16(o[2 * nb + hh], ph, vh[2 * hh], vh[2 * hh + 1]);
            }
        }
        __syncthreads();
    }

    // ---- epilogue ----
    float inv0 = 1.0f / l0, inv1 = 1.0f / l1;
    int mr0 = q0 + wid * 16 + g;
#pragma unroll
    for (int nf = 0; nf < 8; nf++) {
        int d = h * 64 + nf * 8 + tq * 2;
        size_t i0 = ((size_t)b * 2048 + mr0) * 1024 + d;
        size_t i1 = i0 + 8 * 1024;
        *(__half2*)(Out + i0) = __float22half2_rn(
            make_float2(o[nf][0] * inv0, o[nf][1] * inv0));
        *(__half2*)(Out + i1) = __float22half2_rn(
            make_float2(o[nf][2] * inv1, o[nf][3] * inv1));
    }
}

// ---------------------------------------------------------------------------
extern "C" void kernel_launch(void* const* d_in, const int* in_sizes, int n_in,
                              void* d_out, int out_size) {
    const float* x      = (const float*)d_in[0];  // (2, 2048, 1024)
    const float* W_attn = (const float*)d_in[1];  // (1024, 3072)
    const float* b_attn = (const float*)d_in[2];  // (3072,)
    const float* W_proj = (const float*)d_in[3];  // (1024, 1024)
    const float* b_proj = (const float*)d_in[4];  // (1024,)
    float* out = (float*)d_out;                   // (2, 2048, 1024)

    __half *xs, *ks, *att, *wk, *wp;
    cudaGetSymbolAddress((void**)&xs, g_xs);
    cudaGetSymbolAddress((void**)&ks, g_ks);
    cudaGetSymbolAddress((void**)&att, g_att);
    cudaGetSymbolAddress((void**)&wk, g_wk);
    cudaGetSymbolAddress((void**)&wp, g_wp);

    cudaFuncSetAttribute(gemm_mma,
                         cudaFuncAttributeMaxDynamicSharedMemorySize, G2_SMEM);
    cudaFuncSetAttribute(attn_mma,
                         cudaFuncAttributeMaxDynamicSharedMemorySize, ATTN_SMEM_B);

    // Prep (one launch)
    prep_kernel<<<6144, 256>>>(x, xs, W_attn + 1024, W_proj, wk, wp);

    // Stage 1: K = x @ W_attn[:, D:2D] + b  -> single fp16
    gemm_mma<<<dim3(8, 16), 512, G2_SMEM>>>(xs, wk, b_attn + 1024, nullptr, ks);

    // Stage 2: FA2 attention -> att fp16
    attn_mma<<<dim3(16, 32), 256, ATTN_SMEM_B>>>(ks, att);

    // Stage 3: out = att @ W_proj + b_proj (fp32 out)
    gemm_mma<<<dim3(8, 16), 512, G2_SMEM>>>(att, wp, b_proj, out, nullptr);
}

// round 15
// speedup vs baseline: 1.0557x; 1.0256x over previous
#include <cuda_runtime.h>
#include <cuda_fp16.h>
#include <cstdint>

// ---------------- scratch (__device__ globals; no allocation allowed) -------
__device__ __half g_xs[4096 * 1024];            // x as fp16
__device__ __half g_ks[4096 * 1024];            // K projection fp16
__device__ __half g_att[4096 * 1024];           // attention out fp16
__device__ __half g_wk[1024 * 1024];            // W_attn K-slice, [n][k] fp16
__device__ __half g_wp[1024 * 1024];            // W_proj, [n][k] fp16

// ---------------- PTX helpers (all compute_103-safe) ------------------------
__device__ __forceinline__ float fast_exp2(float x) {
    float y; asm("ex2.approx.ftz.f32 %0, %1;" : "=f"(y) : "f"(x)); return y;
}
__device__ __forceinline__ uint32_t smem_u32(const void* p) {
    uint32_t a;
    asm("{ .reg .u64 t; cvta.to.shared.u64 t, %1; cvt.u32.u64 %0, t; }" : "=r"(a) : "l"(p));
    return a;
}
__device__ __forceinline__ void cp_async16(uint32_t dst, const void* src) {
    asm volatile("cp.async.cg.shared.global [%0], [%1], 16;" :: "r"(dst), "l"(src));
}
__device__ __forceinline__ void cp_commit() {
    asm volatile("cp.async.commit_group;" ::: "memory");
}
__device__ __forceinline__ void cp_wait1() {
    asm volatile("cp.async.wait_group 1;" ::: "memory");
}
__device__ __forceinline__ void cp_wait2() {
    asm volatile("cp.async.wait_group 2;" ::: "memory");
}
__device__ __forceinline__ void cp_wait0() {
    asm volatile("cp.async.wait_group 0;" ::: "memory");
}
__device__ __forceinline__ void ldsm4(uint32_t& r0, uint32_t& r1, uint32_t& r2,
                                      uint32_t& r3, uint32_t addr) {
    asm volatile("ldmatrix.sync.aligned.m8n8.x4.shared.b16 {%0,%1,%2,%3}, [%4];"
                 : "=r"(r0), "=r"(r1), "=r"(r2), "=r"(r3) : "r"(addr));
}
__device__ __forceinline__ void ldsm4t(uint32_t& r0, uint32_t& r1, uint32_t& r2,
                                       uint32_t& r3, uint32_t addr) {
    asm volatile("ldmatrix.sync.aligned.m8n8.x4.trans.shared.b16 {%0,%1,%2,%3}, [%4];"
                 : "=r"(r0), "=r"(r1), "=r"(r2), "=r"(r3) : "r"(addr));
}
__device__ __forceinline__ void mma_f16(float* c, const uint32_t* a,
                                        uint32_t b0, uint32_t b1) {
    asm volatile(
        "mma.sync.aligned.m16n8k16.row.col.f32.f16.f16.f32 "
        "{%0,%1,%2,%3}, {%4,%5,%6,%7}, {%8,%9}, {%0,%1,%2,%3};"
        : "+f"(c[0]), "+f"(c[1]), "+f"(c[2]), "+f"(c[3])
        : "r"(a[0]), "r"(a[1]), "r"(a[2]), "r"(a[3]), "r"(b0), "r"(b1));
}
__device__ __forceinline__ uint32_t pack_h2(float a, float b) {
    __half2 h = __float22half2_rn(make_float2(a, b));
    return *(uint32_t*)&h;
}

// ---------------- merged prep: x->fp16; W transposes (single fp16) ----------
__global__ __launch_bounds__(256) void prep_kernel(
    const float* __restrict__ X, __half* __restrict__ XO,
    const float* __restrict__ Wk, const float* __restrict__ Wp,
    __half* __restrict__ WkO, __half* __restrict__ WpO)
{
    __shared__ float t[32][33];
    int bid = blockIdx.x;
    if (bid < 4096) {
        int i = bid * 256 + threadIdx.x;
        float4 v = ((const float4*)X)[i];
        ((__half2*)XO)[i * 2]     = __float22half2_rn(make_float2(v.x, v.y));
        ((__half2*)XO)[i * 2 + 1] = __float22half2_rn(make_float2(v.z, v.w));
        return;
    }
    bid -= 4096;
    const float* W; __half* O; int ldw;
    if (bid < 1024) { W = Wk; ldw = 3072; O = WkO; }
    else { bid -= 1024; W = Wp; ldw = 1024; O = WpO; }
    int n0 = (bid & 31) * 32, k0 = (bid >> 5) * 32;
    int tx = threadIdx.x & 31, ty = threadIdx.x >> 5;
#pragma unroll
    for (int p = 0; p < 4; p++)
        t[ty + 8 * p][tx] = W[(size_t)(k0 + ty + 8 * p) * ldw + n0 + tx];
    __syncthreads();
#pragma unroll
    for (int p = 0; p < 4; p++)
        O[(size_t)(n0 + ty + 8 * p) * 1024 + k0 + tx] =
            __float2half_rn(t[tx][ty + 8 * p]);
}

// ---------------- tensor-core GEMM: C = A @ B^T + bias (single fp16) --------
// Tile M=256, N=128, BK=32, 512 threads (16 warps, warp 64x32), 4-stage
// cp.async pipeline, ONE CTA per SM (128 CTAs, single balanced wave).
// Loader addressing fully hoisted: per-thread 3 fixed (src, dst) pairs;
// per chunk only src += 64.
#define G2_ROWB 80
#define G2_STAGE 30720
#define G2_SMEM (4 * G2_STAGE)   // 122880

__global__ __launch_bounds__(512, 1) void gemm_mma(
    const __half* __restrict__ A, const __half* __restrict__ B,
    const float* __restrict__ bias, float* __restrict__ C,
    __half* __restrict__ Ch)
{
    extern __shared__ char smem[];
    const uint32_t sb = smem_u32(smem);
    const int tid = threadIdx.x;
    const int wid = tid >> 5;       // 0..15
    const int lane = tid & 31;
    const int wm = wid >> 2;        // 0..3, 64 rows each
    const int wn = wid & 3;         // 0..3, 32 cols each
    const int m0 = blockIdx.y * 256, n0 = blockIdx.x * 128;

    const uint32_t a_off = (uint32_t)((wm * 64 + (lane & 15)) * G2_ROWB + (lane >> 4) * 16);
    const uint32_t b_off = (uint32_t)(256 * G2_ROWB
                                      + (wn * 32 + (lane & 15)) * G2_ROWB + (lane >> 4) * 16);

    // ---- hoisted loader addressing: 3 fixed (src, dst) pairs per thread ----
    const char* lsrc[3];
    uint32_t ldst[3];
#pragma unroll
    for (int p = 0; p < 3; p++) {
        int u = tid + p * 512;
        int row = u >> 2, c16 = u & 3;
        lsrc[p] = (row < 256)
            ? (const char*)A + (size_t)(m0 + row) * 2048 + c16 * 16
            : (const char*)B + (size_t)(n0 + row - 256) * 2048 + c16 * 16;
        ldst[p] = sb + (uint32_t)(row * G2_ROWB + c16 * 16);
    }

    float acc[4][4][4];
#pragma unroll
    for (int i = 0; i < 4; i++)
#pragma unroll
        for (int j = 0; j < 4; j++)
#pragma unroll
            for (int r = 0; r < 4; r++) acc[i][j][r] = 0.0f;

    // prologue: chunks 0,1,2
#pragma unroll
    for (int c = 0; c < 3; c++) {
        const uint32_t stg = (uint32_t)c * G2_STAGE;
#pragma unroll
        for (int p = 0; p < 3; p++)
            cp_async16(ldst[p] + stg, lsrc[p] + c * 64);
        cp_commit();
    }

    for (int c = 0; c < 32; c++) {
        cp_wait2();           // chunk c's group complete
        __syncthreads();
        if (c + 3 < 32) {
            const uint32_t stg = (uint32_t)((c + 3) & 3) * G2_STAGE;
#pragma unroll
            for (int p = 0; p < 3; p++)
                cp_async16(ldst[p] + stg, lsrc[p] + (c + 3) * 64);
        }
        cp_commit();

        const uint32_t st = (uint32_t)(c & 3) * G2_STAGE;
#pragma unroll
        for (int kk = 0; kk < 2; kk++) {
            uint32_t bh[2][4];
#pragma unroll
            for (int p = 0; p < 2; p++) {
                uint32_t addr = sb + st + b_off + (uint32_t)(p * 16 * G2_ROWB) + kk * 32;
                ldsm4(bh[p][0], bh[p][1], bh[p][2], bh[p][3], addr);
            }
            uint32_t ah[4][4];
#pragma unroll
            for (int mf = 0; mf < 4; mf++) {
                uint32_t addr = sb + st + a_off + (uint32_t)(mf * 16 * G2_ROWB) + kk * 32;
                ldsm4(ah[mf][0], ah[mf][1], ah[mf][2], ah[mf][3], addr);
            }
#pragma unroll
            for (int mf = 0; mf < 4; mf++)
#pragma unroll
                for (int nf = 0; nf < 4; nf++) {
                    const int p = nf >> 1, hh = nf & 1;
                    mma_f16(acc[mf][nf], ah[mf], bh[p][hh], bh[p][2 + hh]);
                }
        }
    }

    // epilogue
#pragma unroll
    for (int nf = 0; nf < 4; nf++) {
        int n = n0 + wn * 32 + nf * 8 + (lane & 3) * 2;
        float2 bv = *(const float2*)(bias + n);
#pragma unroll
        for (int mf = 0; mf < 4; mf++) {
            int m = m0 + wm * 64 + mf * 16 + (lane >> 2);
            float2 o0 = {acc[mf][nf][0] + bv.x, acc[mf][nf][1] + bv.y};
            float2 o1 = {acc[mf][nf][2] + bv.x, acc[mf][nf][3] + bv.y};
            if (Ch) {
                *(__half2*)(Ch + (size_t)m * 1024 + n) =
                    __float22half2_rn(make_float2(o0.x, o0.y));
                *(__half2*)(Ch + (size_t)(m + 8) * 1024 + n) =
                    __float22half2_rn(make_float2(o1.x, o1.y));
            } else {
                *(float2*)(C + (size_t)m * 1024 + n) = o0;
                *(float2*)(C + (size_t)(m + 8) * 1024 + n) = o1;
            }
        }
    }
}

// ---------------- FA2-style attention (single-fp16 K throughout) ------------
#define ROWB 144
#define AK0 18432
#define AKST 18432
#define ATTN_SMEM_B (18432 + 2 * 18432)

__global__ __launch_bounds__(256, 2) void attn_mma(
    const __half* __restrict__ K, __half* __restrict__ Out)
{
    extern __shared__ char smem[];
    const uint32_t sb = smem_u32(smem);
    const int tid = threadIdx.x;
    const int wid = tid >> 5;
    const int lane = tid & 31;
    const int g = lane >> 2;
    const int tq = lane & 3;
    const int b = blockIdx.y >> 4;
    const int h = blockIdx.y & 15;
    const int q0 = blockIdx.x * 128;

    const char* Kb = (const char*)K + (size_t)b * 2048 * 2048 + h * 128;
    const float SC = 0.125f * 1.4426950408889634f;

#pragma unroll
    for (int q = 0; q < 4; q++) {
        int u = tid + q * 256;
        int row = u >> 3, c = u & 7;
        cp_async16(sb + row * ROWB + c * 16,
                   Kb + (size_t)(q0 + row) * 2048 + c * 16);
    }
#pragma unroll
    for (int q = 0; q < 4; q++) {
        int u = tid + q * 256;
        int row = u >> 3, c = u & 7;
        cp_async16(sb + AK0 + row * ROWB + c * 16, Kb + (size_t)row * 2048 + c * 16);
    }
    cp_commit();

    float m0 = -1e30f, m1 = -1e30f, l0 = 0.0f, l1 = 0.0f;
    float o[8][4];
#pragma unroll
    for (int nf = 0; nf < 8; nf++)
#pragma unroll
        for (int r = 0; r < 4; r++) o[nf][r] = 0.0f;

    const uint32_t qa_off = (uint32_t)((wid * 16 + (lane & 15)) * ROWB + (lane >> 4) * 16);
    const uint32_t kb_row = (uint32_t)((lane & 15) * ROWB + (lane >> 4) * 16);

    for (int kt = 0; kt < 16; kt++) {
        const uint32_t st = sb + AK0 + (uint32_t)(kt & 1) * AKST;
        if (kt + 1 < 16) {
            const uint32_t st2 = sb + AK0 + (uint32_t)((kt + 1) & 1) * AKST;
            const size_t j0 = (size_t)(kt + 1) * 128;
#pragma unroll
            for (int q = 0; q < 4; q++) {
                int u = tid + q * 256;
                int row = u >> 3, c = u & 7;
                cp_async16(st2 + row * ROWB + c * 16, Kb + (j0 + row) * 2048 + c * 16);
            }
            cp_commit();
            cp_wait1();
        } else {
            cp_wait0();
        }
        __syncthreads();

        // ---- S = Q K^T ----
        float s[16][4];
#pragma unroll
        for (int nf = 0; nf < 16; nf++)
#pragma unroll
            for (int r = 0; r < 4; r++) s[nf][r] = 0.0f;

#pragma unroll
        for (int kk = 0; kk < 4; kk++) {
            uint32_t qh[4];
            ldsm4(qh[0], qh[1], qh[2], qh[3], sb + qa_off + kk * 32);
#pragma unroll
            for (int nb = 0; nb < 8; nb++) {
                uint32_t kh[4];
                uint32_t addr = st + kb_row + (uint32_t)(nb * 16 * ROWB) + kk * 32;
                ldsm4(kh[0], kh[1], kh[2], kh[3], addr);
#pragma unroll
                for (int hh = 0; hh < 2; hh++)
                    mma_f16(s[2 * nb + hh], qh, kh[hh], kh[2 + hh]);
            }
        }

        // ---- online softmax (scale folded) ----
        float mx0 = -1e30f, mx1 = -1e30f;
#pragma unroll
        for (int nf = 0; nf < 16; nf++) {
            mx0 = fmaxf(mx0, fmaxf(s[nf][0], s[nf][1]));
            mx1 = fmaxf(mx1, fmaxf(s[nf][2], s[nf][3]));
        }
        mx0 = fmaxf(mx0, __shfl_xor_sync(0xffffffffu, mx0, 1));
        mx0 = fmaxf(mx0, __shfl_xor_sync(0xffffffffu, mx0, 2));
        mx1 = fmaxf(mx1, __shfl_xor_sync(0xffffffffu, mx1, 1));
        mx1 = fmaxf(mx1, __shfl_xor_sync(0xffffffffu, mx1, 2));
        float mn0 = fmaxf(m0, mx0), mn1 = fmaxf(m1, mx1);
        float c0 = fast_exp2((m0 - mn0) * SC), c1 = fast_exp2((m1 - mn1) * SC);
        m0 = mn0; m1 = mn1;
        l0 *= c0; l1 *= c1;
#pragma unroll
        for (int nf = 0; nf < 8; nf++) {
            o[nf][0] *= c0; o[nf][1] *= c0;
            o[nf][2] *= c1; o[nf][3] *= c1;
        }
        const float b0s = -mn0 * SC, b1s = -mn1 * SC;
        float rs0 = 0.0f, rs1 = 0.0f;
#pragma unroll
        for (int nf = 0; nf < 16; nf++) {
            s[nf][0] = fast_exp2(fmaf(s[nf][0], SC, b0s));
            s[nf][1] = fast_exp2(fmaf(s[nf][1], SC, b0s));
            s[nf][2] = fast_exp2(fmaf(s[nf][2], SC, b1s));
            s[nf][3] = fast_exp2(fmaf(s[nf][3], SC, b1s));
            rs0 += s[nf][0] + s[nf][1];
            rs1 += s[nf][2] + s[nf][3];
        }
        rs0 += __shfl_xor_sync(0xffffffffu, rs0, 1);
        rs0 += __shfl_xor_sync(0xffffffffu, rs0, 2);
        rs1 += __shfl_xor_sync(0xffffffffu, rs1, 1);
        rs1 += __shfl_xor_sync(0xffffffffu, rs1, 2);
        l0 += rs0; l1 += rs1;

        // ---- O += P V (single term; V via ldsm.trans) ----
#pragma unroll
        for (int t = 0; t < 8; t++) {
            uint32_t ph[4];
            ph[0] = pack_h2(s[2 * t][0], s[2 * t][1]);
            ph[1] = pack_h2(s[2 * t][2], s[2 * t][3]);
            ph[2] = pack_h2(s[2 * t + 1][0], s[2 * t + 1][1]);
            ph[3] = pack_h2(s[2 * t + 1][2], s[2 * t + 1][3]);
#pragma unroll
            for (int nb = 0; nb < 4; nb++) {
                uint32_t vh[4];
                uint32_t addr = st + kb_row + (uint32_t)(t * 16 * ROWB) + nb * 32;
                ldsm4t(vh[0], vh[1], vh[2], vh[3], addr);
#pragma unroll
                for (int hh = 0; hh < 2; hh++)
                    mma_f16(o[2 * nb + hh], ph, vh[2 * hh], vh[2 * hh + 1]);
            }
        }
        __syncthreads();
    }

    // ---- epilogue ----
    float inv0 = 1.0f / l0, inv1 = 1.0f / l1;
    int mr0 = q0 + wid * 16 + g;
#pragma unroll
    for (int nf = 0; nf < 8; nf++) {
        int d = h * 64 + nf * 8 + tq * 2;
        size_t i0 = ((size_t)b * 2048 + mr0) * 1024 + d;
        size_t i1 = i0 + 8 * 1024;
        *(__half2*)(Out + i0) = __float22half2_rn(
            make_float2(o[nf][0] * inv0, o[nf][1] * inv0));
        *(__half2*)(Out + i1) = __float22half2_rn(
            make_float2(o[nf][2] * inv1, o[nf][3] * inv1));
    }
}

// ---------------------------------------------------------------------------
extern "C" void kernel_launch(void* const* d_in, const int* in_sizes, int n_in,
                              void* d_out, int out_size) {
    const float* x      = (const float*)d_in[0];  // (2, 2048, 1024)
    const float* W_attn = (const float*)d_in[1];  // (1024, 3072)
    const float* b_attn = (const float*)d_in[2];  // (3072,)
    const float* W_proj = (const float*)d_in[3];  // (1024, 1024)
    const float* b_proj = (const float*)d_in[4];  // (1024,)
    float* out = (float*)d_out;                   // (2, 2048, 1024)

    __half *xs, *ks, *att, *wk, *wp;
    cudaGetSymbolAddress((void**)&xs, g_xs);
    cudaGetSymbolAddress((void**)&ks, g_ks);
    cudaGetSymbolAddress((void**)&att, g_att);
    cudaGetSymbolAddress((void**)&wk, g_wk);
    cudaGetSymbolAddress((void**)&wp, g_wp);

    cudaFuncSetAttribute(gemm_mma,
                         cudaFuncAttributeMaxDynamicSharedMemorySize, G2_SMEM);
    cudaFuncSetAttribute(attn_mma,
                         cudaFuncAttributeMaxDynamicSharedMemorySize, ATTN_SMEM_B);

    // Prep (one launch)
    prep_kernel<<<6144, 256>>>(x, xs, W_attn + 1024, W_proj, wk, wp);

    // Stage 1: K = x @ W_attn[:, D:2D] + b  -> single fp16
    gemm_mma<<<dim3(8, 16), 512, G2_SMEM>>>(xs, wk, b_attn + 1024, nullptr, ks);

    // Stage 2: FA2 attention -> att fp16
    attn_mma<<<dim3(16, 32), 256, ATTN_SMEM_B>>>(ks, att);

    // Stage 3: out = att @ W_proj + b_proj (fp32 out)
    gemm_mma<<<dim3(8, 16), 512, G2_SMEM>>>(att, wp, b_proj, out, nullptr);
}